// round 5
// baseline (speedup 1.0000x reference)
#include <cuda_runtime.h>
#include <cstdint>

#define DIMS 64
#define SVOL (64*64*64)
#define NBATCH 4
#define NCLASS 4
#define NPAIR 12
#define NVOL 24
#define NTOT (NBATCH*SVOL)
#define INF_SENT 1e12f
#define SMOOTHV 1e-5f

#define K2_UNITS (NVOL * 64)         // 1536 slices
#define K3_UNITS (NPAIR * 128)       // 1536 (pair, h, half) units
#define K2_GRID  444                 // 3 blocks/SM persistent
#define K3_GRID  740                 // 5 blocks/SM persistent

__device__ float g_F [(size_t)NVOL * SVOL];
__device__ float g_F2[(size_t)NVOL * SVOL];
__device__ float g_prob[(size_t)NPAIR * SVOL];
__device__ float g_TP[16];
__device__ float g_PS[16];
__device__ float g_CNT[16];
__device__ float g_focal;
__device__ float g_bsum[NPAIR];
__device__ int   g_flag64;
__device__ unsigned g_u2, g_u3;      // work-steal counters

__device__ __forceinline__ void cp_async16(uint32_t dst, const float* src) {
    asm volatile("cp.async.cg.shared.global [%0], [%1], 16;" :: "r"(dst), "l"(src));
}

// ============================================================
// K0
// ============================================================
__global__ void k0_init(const int* __restrict__ tgt32) {
    int t = threadIdx.x;
    __shared__ int any;
    if (t == 0) any = 0;
    __syncthreads();
    int v = tgt32[2 * t + 1];
    if (v != 0) atomicOr(&any, 1);
    __syncthreads();
    if (t == 0) g_flag64 = (any == 0) ? 1 : 0;
    if (t < 16) { g_TP[t] = 0.f; g_PS[t] = 0.f; g_CNT[t] = 0.f; }
    if (t < NPAIR) g_bsum[t] = 0.f;
    if (t == 0) { g_focal = 0.f; g_u2 = 0u; g_u3 = 0u; }
}

__device__ __forceinline__ float nd2(unsigned long long M, int i) {
    if (M == 0ULL) return INF_SENT;
    unsigned long long L = M << (63 - i);
    int dl = L ? __clzll((long long)L) : 9999;
    unsigned long long R = M >> i;
    int dr = R ? (__ffsll((long long)R) - 1) : 9999;
    int d = min(dl, dr);
    return (float)(d * d);
}

// ============================================================
// K1: softmax, focal, Tversky partials, prob store, EDT pass-1 (W)
// ============================================================
__global__ void __launch_bounds__(256) k1_main(const float* __restrict__ preds,
                                               const int* __restrict__ tgt32) {
    const int tid = threadIdx.x;
    const int g = blockIdx.x * 256 + tid;
    const int b = g >> 18;
    const int s = g & (SVOL - 1);

    const int f64 = g_flag64;
    const int t = tgt32[f64 ? (g << 1) : g];

    const float x0 = preds[(size_t)(b * 4 + 0) * SVOL + s];
    const float x1 = preds[(size_t)(b * 4 + 1) * SVOL + s];
    const float x2 = preds[(size_t)(b * 4 + 2) * SVOL + s];
    const float x3 = preds[(size_t)(b * 4 + 3) * SVOL + s];

    const float m  = fmaxf(fmaxf(x0, x1), fmaxf(x2, x3));
    const float e0 = expf(x0 - m), e1 = expf(x1 - m);
    const float e2 = expf(x2 - m), e3 = expf(x3 - m);
    const float se = e0 + e1 + e2 + e3;
    const float inv = 1.0f / se;
    const float p0 = e0 * inv, p1 = e1 * inv, p2 = e2 * inv, p3 = e3 * inv;

    const float xt = (t == 0) ? x0 : (t == 1) ? x1 : (t == 2) ? x2 : x3;
    const float ce = -(xt - m - logf(se));
    const float pt = (t == 0) ? p0 : (t == 1) ? p1 : (t == 2) ? p2 : p3;
    const float om = 1.0f - pt;
    const float focal = om * om * ce;

    g_prob[(size_t)(b * 3 + 0) * SVOL + s] = p1;
    g_prob[(size_t)(b * 3 + 1) * SVOL + s] = p2;
    g_prob[(size_t)(b * 3 + 2) * SVOL + s] = p3;

    const unsigned full = 0xFFFFFFFFu;
    const unsigned bal1 = __ballot_sync(full, t == 1);
    const unsigned bal2 = __ballot_sync(full, t == 2);
    const unsigned bal3 = __ballot_sync(full, t == 3);
    __shared__ unsigned sb[3][8];
    const int wid = tid >> 5;
    if ((tid & 31) == 0) { sb[0][wid] = bal1; sb[1][wid] = bal2; sb[2][wid] = bal3; }
    __syncthreads();

    const int line = tid >> 6;
    const int i = tid & 63;
#pragma unroll
    for (int cm = 0; cm < 3; cm++) {
        unsigned long long M = (unsigned long long)sb[cm][line * 2] |
                               ((unsigned long long)sb[cm][line * 2 + 1] << 32);
        const int v = (b * 3 + cm) * 2;
        g_F[(size_t)v * SVOL + s]       = nd2(M, i);
        g_F[(size_t)(v + 1) * SVOL + s] = nd2(~M, i);
    }

    float vals[13];
    vals[0] = (t == 0) ? p0 : 0.f;
    vals[1] = (t == 1) ? p1 : 0.f;
    vals[2] = (t == 2) ? p2 : 0.f;
    vals[3] = (t == 3) ? p3 : 0.f;
    vals[4] = p0; vals[5] = p1; vals[6] = p2; vals[7] = p3;
    vals[8]  = (t == 0) ? 1.f : 0.f;
    vals[9]  = (t == 1) ? 1.f : 0.f;
    vals[10] = (t == 2) ? 1.f : 0.f;
    vals[11] = (t == 3) ? 1.f : 0.f;
    vals[12] = focal;

    __shared__ float red[13 * 8];
#pragma unroll
    for (int q = 0; q < 13; q++) {
        float v = vals[q];
#pragma unroll
        for (int o = 16; o > 0; o >>= 1) v += __shfl_down_sync(full, v, o);
        if ((tid & 31) == 0) red[q * 8 + wid] = v;
    }
    __syncthreads();
    if (tid < 13) {
        float sum = 0.f;
#pragma unroll
        for (int k = 0; k < 8; k++) sum += red[tid * 8 + k];
        if (tid < 4)       atomicAdd(&g_TP[b * 4 + tid], sum);
        else if (tid < 8)  atomicAdd(&g_PS[b * 4 + tid - 4], sum);
        else if (tid < 12) atomicAdd(&g_CNT[b * 4 + tid - 8], sum);
        else               atomicAdd(&g_focal, sum);
    }
}

// ============================================================
// K2: EDT pass along H (g_F -> g_F2). Persistent 512-thread
// blocks with atomic work-stealing over 1536 slices.
// ============================================================
__global__ void __launch_bounds__(512, 3) k2_passH() {
    __shared__ __align__(16) float T[4096];
    __shared__ unsigned su;
    const int tid = threadIdx.x;
    const int w = tid & 63;
    const int gq = tid >> 6;

    for (;;) {
        if (tid == 0) su = atomicAdd(&g_u2, 1u);
        __syncthreads();                    // su visible; prev T reads done
        const unsigned unit = su;
        if (unit >= K2_UNITS) return;
        const int v = unit >> 6;
        const int d = unit & 63;
        const size_t base = (size_t)v * SVOL + (size_t)d * 4096;

        const float4* src = reinterpret_cast<const float4*>(g_F + base);
        float4* Tv = reinterpret_cast<float4*>(T);
#pragma unroll
        for (int r = 0; r < 2; r++) {
            int m = tid + r * 512;
            float4 val = src[m];
            float jv = (float)(m >> 4);
            float j2 = jv * jv;
            val.x += j2; val.y += j2; val.z += j2; val.w += j2;
            Tv[m] = val;
        }
        __syncthreads();

        float acc[8], ck[8];
#pragma unroll
        for (int k = 0; k < 8; k++) {
            acc[k] = 3.0e38f;
            ck[k] = -2.0f * (float)(gq + 8 * k);
        }
        float jf = 0.f;
#pragma unroll 8
        for (int j = 0; j < 64; j++, jf += 1.0f) {
            const float gj = T[j * 64 + w];
#pragma unroll
            for (int k = 0; k < 8; k++)
                acc[k] = fminf(acc[k], fmaf(ck[k], jf, gj));
        }
#pragma unroll
        for (int k = 0; k < 8; k++) {
            const int i = gq + 8 * k;
            g_F2[base + (size_t)i * 64 + w] = acc[k] + (float)(i * i);
        }
    }
}

// ============================================================
// K3: EDT pass along D + sdf*prob reduction. Persistent
// 256-thread blocks, 5/SM, work-stealing over 1536 units.
// ============================================================
__global__ void __launch_bounds__(256, 5) k3_passD() {
    __shared__ __align__(16) float To[4096];
    __shared__ __align__(16) float Ti[4096];
    __shared__ float red[8];
    __shared__ unsigned su;
    const int tid = threadIdx.x;
    const int w = tid & 63;
    const int gq = tid >> 6;
    const uint32_t tib = (uint32_t)__cvta_generic_to_shared(Ti);

    for (;;) {
        if (tid == 0) su = atomicAdd(&g_u3, 1u);
        __syncthreads();
        const unsigned unit = su;
        if (unit >= K3_UNITS) return;
        const int p    = unit >> 7;
        const int rem  = unit & 127;
        const int h    = rem >> 1;
        const int half = rem & 1;
        const int ib = half * 32 + gq;
        const size_t baseO = (size_t)(2 * p) * SVOL + (size_t)h * 64;
        const size_t baseI = baseO + SVOL;

        // ---- prefetch IN tile (raw) via cp.async ----
#pragma unroll
        for (int r = 0; r < 4; r++) {
            int m = tid + r * 256;
            int dd = m >> 4;
            int w0 = (4 * m) & 63;
            cp_async16(tib + m * 16, &g_F2[baseI + (size_t)dd * 4096 + w0]);
        }
        asm volatile("cp.async.commit_group;");

        // ---- load OUT tile, fold +j^2 ----
#pragma unroll
        for (int r = 0; r < 4; r++) {
            int m = tid + r * 256;
            int dd = m >> 4;
            int w0 = (4 * m) & 63;
            float4 val = *reinterpret_cast<const float4*>(&g_F2[baseO + (size_t)dd * 4096 + w0]);
            float jv = (float)dd, j2 = jv * jv;
            val.x += j2; val.y += j2; val.z += j2; val.w += j2;
            reinterpret_cast<float4*>(To)[m] = val;
        }
        __syncthreads();

        float ro[8];
        {
            float acc[8], ck[8];
#pragma unroll
            for (int k = 0; k < 8; k++) { acc[k] = 3.0e38f; ck[k] = -2.0f * (float)(ib + 4 * k); }
            float jf = 0.f;
#pragma unroll 8
            for (int j = 0; j < 64; j++, jf += 1.0f) {
                const float gj = To[j * 64 + w];
#pragma unroll
                for (int k = 0; k < 8; k++)
                    acc[k] = fminf(acc[k], fmaf(ck[k], jf, gj));
            }
#pragma unroll
            for (int k = 0; k < 8; k++) {
                const int i = ib + 4 * k;
                ro[k] = acc[k] + (float)(i * i);
            }
        }

        // ---- fold own IN elements, barrier ----
        asm volatile("cp.async.wait_group 0;");
#pragma unroll
        for (int r = 0; r < 4; r++) {
            int m = tid + r * 256;
            float jv = (float)(m >> 4), j2 = jv * jv;
            float4 val = reinterpret_cast<float4*>(Ti)[m];
            val.x += j2; val.y += j2; val.z += j2; val.w += j2;
            reinterpret_cast<float4*>(Ti)[m] = val;
        }
        __syncthreads();

        float local = 0.f;
        {
            float acc[8], ck[8];
#pragma unroll
            for (int k = 0; k < 8; k++) { acc[k] = 3.0e38f; ck[k] = -2.0f * (float)(ib + 4 * k); }
            float jf = 0.f;
#pragma unroll 8
            for (int j = 0; j < 64; j++, jf += 1.0f) {
                const float gj = Ti[j * 64 + w];
#pragma unroll
                for (int k = 0; k < 8; k++)
                    acc[k] = fminf(acc[k], fmaf(ck[k], jf, gj));
            }
#pragma unroll
            for (int k = 0; k < 8; k++) {
                const int i = ib + 4 * k;
                const float ri = acc[k] + (float)(i * i);
                const float sdf = sqrtf(ro[k]) - sqrtf(ri);
                const float pr = g_prob[(size_t)p * SVOL + (size_t)i * 4096 + (size_t)h * 64 + w];
                local = fmaf(sdf, pr, local);
            }
        }

#pragma unroll
        for (int o = 16; o > 0; o >>= 1) local += __shfl_down_sync(0xFFFFFFFFu, local, o);
        const int wid = tid >> 5;
        if ((tid & 31) == 0) red[wid] = local;
        __syncthreads();
        if (tid == 0) {
            float sum = 0.f;
#pragma unroll
            for (int k = 0; k < 8; k++) sum += red[k];
            atomicAdd(&g_bsum[p], sum);
        }
    }
}

// ============================================================
// K4
// ============================================================
__global__ void k4_final(float* out) {
    if (threadIdx.x == 0) {
        float dice = 0.f;
        for (int bc = 0; bc < 16; bc++) {
            const float TP = g_TP[bc], PS = g_PS[bc], CNT = g_CNT[bc];
            const float FP = PS - TP;
            const float FN = CNT - TP;
            dice += (TP + SMOOTHV) / (TP + 0.3f * FP + 0.7f * FN + SMOOTHV);
        }
        const float l_dice = 1.0f - dice / 16.0f;
        const float l_main = g_focal / (float)NTOT;

        float bacc = 0.f;
        for (int p = 0; p < NPAIR; p++) {
            const int b = p / 3, c = p % 3 + 1;
            const float cnt = g_CNT[b * 4 + c];
            if (cnt > 0.f) {
                float contrib;
                if (cnt >= (float)SVOL)
                    contrib = -g_PS[b * 4 + c] / (float)SVOL;
                else
                    contrib = g_bsum[p] / (float)SVOL;
                bacc += contrib;
            }
        }
        const float l_bound = bacc / (12.0f + 1e-8f);
        out[0] = l_dice + l_main + 0.01f * l_bound;
    }
}

extern "C" void kernel_launch(void* const* d_in, const int* in_sizes, int n_in,
                              void* d_out, int out_size) {
    const float* preds = (const float*)d_in[0];
    const int*   tgt   = (const int*)d_in[1];
    (void)in_sizes; (void)n_in; (void)out_size;

    k0_init<<<1, 256>>>(tgt);
    k1_main<<<NTOT / 256, 256>>>(preds, tgt);
    k2_passH<<<K2_GRID, 512>>>();
    k3_passD<<<K3_GRID, 256>>>();
    k4_final<<<1, 32>>>((float*)d_out);
}

// round 6
// speedup vs baseline: 2.2430x; 2.2430x over previous
#include <cuda_runtime.h>
#include <cuda_fp16.h>
#include <cstdint>

#define DIMS 64
#define SVOL (64*64*64)
#define NBATCH 4
#define NCLASS 4
#define NPAIR 12
#define NVOL 24
#define NTOT (NBATCH*SVOL)
#define SMOOTHV 1e-5f

__device__ __half g_Fh [(size_t)NVOL * SVOL];    // pass-1 line distances (fp16, exact ints)
__device__ __half g_F2h[(size_t)NVOL * SVOL];    // pass-2 2D distances (fp16)
__device__ __half g_probh[(size_t)NPAIR * SVOL]; // probs classes 1..3 (fp16)
__device__ float g_TP[16];
__device__ float g_PS[16];
__device__ float g_CNT[16];
__device__ float g_focal;
__device__ float g_bsum[NPAIR];
__device__ int   g_flag64;

__device__ __forceinline__ float sqrt_ap(float x) {
    float y; asm("sqrt.approx.f32 %0, %1;" : "=f"(y) : "f"(x)); return y;
}

// ============================================================
// K0: zero accumulators + int64-vs-int32 targets detection
// ============================================================
__global__ void k0_init(const int* __restrict__ tgt32) {
    int t = threadIdx.x;
    __shared__ int any;
    if (t == 0) any = 0;
    __syncthreads();
    int v = tgt32[2 * t + 1];
    if (v != 0) atomicOr(&any, 1);
    __syncthreads();
    if (t == 0) g_flag64 = (any == 0) ? 1 : 0;
    if (t < 16) { g_TP[t] = 0.f; g_PS[t] = 0.f; g_CNT[t] = 0.f; }
    if (t < NPAIR) g_bsum[t] = 0.f;
    if (t == 0) g_focal = 0.f;
}

// nearest set-bit distance (not squared) within a 64-bit line mask
__device__ __forceinline__ float ndist(unsigned long long M, int i) {
    if (M == 0ULL) return __int_as_float(0x7f800000);   // +inf
    unsigned long long L = M << (63 - i);
    int dl = L ? __clzll((long long)L) : 9999;
    unsigned long long R = M >> i;
    int dr = R ? (__ffsll((long long)R) - 1) : 9999;
    return (float)min(dl, dr);
}

// ============================================================
// K1: softmax, focal, Tversky partials, prob store (fp16),
//     EDT pass-1 along W via ballot bitmasks -> fp16 distances
// ============================================================
__global__ void __launch_bounds__(256) k1_main(const float* __restrict__ preds,
                                               const int* __restrict__ tgt32) {
    const int tid = threadIdx.x;
    const int g = blockIdx.x * 256 + tid;
    const int b = g >> 18;
    const int s = g & (SVOL - 1);

    const int f64 = g_flag64;
    const int t = tgt32[f64 ? (g << 1) : g];

    const float x0 = preds[(size_t)(b * 4 + 0) * SVOL + s];
    const float x1 = preds[(size_t)(b * 4 + 1) * SVOL + s];
    const float x2 = preds[(size_t)(b * 4 + 2) * SVOL + s];
    const float x3 = preds[(size_t)(b * 4 + 3) * SVOL + s];

    const float m  = fmaxf(fmaxf(x0, x1), fmaxf(x2, x3));
    const float e0 = expf(x0 - m), e1 = expf(x1 - m);
    const float e2 = expf(x2 - m), e3 = expf(x3 - m);
    const float se = e0 + e1 + e2 + e3;
    const float inv = 1.0f / se;
    const float p0 = e0 * inv, p1 = e1 * inv, p2 = e2 * inv, p3 = e3 * inv;

    const float xt = (t == 0) ? x0 : (t == 1) ? x1 : (t == 2) ? x2 : x3;
    const float ce = -(xt - m - logf(se));
    const float pt = (t == 0) ? p0 : (t == 1) ? p1 : (t == 2) ? p2 : p3;
    const float om = 1.0f - pt;
    const float focal = om * om * ce;

    g_probh[(size_t)(b * 3 + 0) * SVOL + s] = __float2half(p1);
    g_probh[(size_t)(b * 3 + 1) * SVOL + s] = __float2half(p2);
    g_probh[(size_t)(b * 3 + 2) * SVOL + s] = __float2half(p3);

    // ---- EDT pass-1 along W via line bitmasks ----
    const unsigned full = 0xFFFFFFFFu;
    const unsigned bal1 = __ballot_sync(full, t == 1);
    const unsigned bal2 = __ballot_sync(full, t == 2);
    const unsigned bal3 = __ballot_sync(full, t == 3);
    __shared__ unsigned sb[3][8];
    const int wid = tid >> 5;
    if ((tid & 31) == 0) { sb[0][wid] = bal1; sb[1][wid] = bal2; sb[2][wid] = bal3; }
    __syncthreads();

    const int line = tid >> 6;
    const int i = tid & 63;
#pragma unroll
    for (int cm = 0; cm < 3; cm++) {
        unsigned long long M = (unsigned long long)sb[cm][line * 2] |
                               ((unsigned long long)sb[cm][line * 2 + 1] << 32);
        const int v = (b * 3 + cm) * 2;
        g_Fh[(size_t)v * SVOL + s]       = __float2half(ndist(M, i));
        g_Fh[(size_t)(v + 1) * SVOL + s] = __float2half(ndist(~M, i));
    }

    float vals[13];
    vals[0] = (t == 0) ? p0 : 0.f;
    vals[1] = (t == 1) ? p1 : 0.f;
    vals[2] = (t == 2) ? p2 : 0.f;
    vals[3] = (t == 3) ? p3 : 0.f;
    vals[4] = p0; vals[5] = p1; vals[6] = p2; vals[7] = p3;
    vals[8]  = (t == 0) ? 1.f : 0.f;
    vals[9]  = (t == 1) ? 1.f : 0.f;
    vals[10] = (t == 2) ? 1.f : 0.f;
    vals[11] = (t == 3) ? 1.f : 0.f;
    vals[12] = focal;

    __shared__ float red[13 * 8];
#pragma unroll
    for (int q = 0; q < 13; q++) {
        float v = vals[q];
#pragma unroll
        for (int o = 16; o > 0; o >>= 1) v += __shfl_down_sync(full, v, o);
        if ((tid & 31) == 0) red[q * 8 + wid] = v;
    }
    __syncthreads();
    if (tid < 13) {
        float sum = 0.f;
#pragma unroll
        for (int k = 0; k < 8; k++) sum += red[tid * 8 + k];
        if (tid < 4)       atomicAdd(&g_TP[b * 4 + tid], sum);
        else if (tid < 8)  atomicAdd(&g_PS[b * 4 + tid - 4], sum);
        else if (tid < 12) atomicAdd(&g_CNT[b * 4 + tid - 8], sum);
        else               atomicAdd(&g_focal, sum);
    }
}

// ============================================================
// Windowed exact 1D DT over 8 contiguous outputs i=c..c+7.
// Window +-3; skipped candidates have dist^2 >= 16 and f^2 >= 0,
// so if warp-max(acc) <= 16 the skip is exact. Otherwise the
// whole warp falls back to the exact full 64-candidate scan.
// ============================================================
template<int STRIDE>
__device__ __forceinline__ void dt8(const __half* __restrict__ base, int c, float acc[8]) {
    const float FINF = __int_as_float(0x7f800000);
    float s[14];
#pragma unroll
    for (int m = 0; m < 14; m++) {
        int j = c - 3 + m;
        float f = (j >= 0 && j < 64) ? __half2float(base[(size_t)j * STRIDE]) : FINF;
        s[m] = f * f;
    }
#pragma unroll
    for (int t = 0; t < 8; t++) {
        float a = s[t + 3];
        a = fminf(a, s[t + 2] + 1.0f); a = fminf(a, s[t + 4] + 1.0f);
        a = fminf(a, s[t + 1] + 4.0f); a = fminf(a, s[t + 5] + 4.0f);
        a = fminf(a, s[t + 0] + 9.0f); a = fminf(a, s[t + 6] + 9.0f);
        acc[t] = a;
    }
    float mx = acc[0];
#pragma unroll
    for (int t = 1; t < 8; t++) mx = fmaxf(mx, acc[t]);
    if (__any_sync(0xFFFFFFFFu, mx > 16.0f)) {
        // exact fallback: full scan (includes window again; min is idempotent)
        float dct[8];
#pragma unroll
        for (int t = 0; t < 8; t++) dct[t] = (float)(c + t);
        float jf = 0.0f;
        for (int j = 0; j < 64; j++, jf += 1.0f) {
            float f = __half2float(base[(size_t)j * STRIDE]);
            float f2 = f * f;
#pragma unroll
            for (int t = 0; t < 8; t++) {
                float dk = dct[t] - jf;
                acc[t] = fminf(acc[t], fmaf(dk, dk, f2));
            }
        }
    }
}

// ============================================================
// K2: EDT pass along H (g_Fh -> g_F2h), windowed. One block per
// (volume, d) slice; thread owns column w, rows c..c+7.
// ============================================================
__global__ void __launch_bounds__(512) k2_passH() {
    const int unit = blockIdx.x;
    const int v = unit >> 6;
    const int d = unit & 63;
    const int tid = threadIdx.x;
    const int w = tid & 63;
    const int c = (tid >> 6) * 8;

    const __half* base = g_Fh + (size_t)v * SVOL + (size_t)d * 4096 + w;
    float acc[8];
    dt8<64>(base, c, acc);

    __half* dst = g_F2h + (size_t)v * SVOL + (size_t)d * 4096 + (size_t)c * 64 + w;
#pragma unroll
    for (int t = 0; t < 8; t++)
        dst[t * 64] = __float2half(sqrt_ap(acc[t]));
}

// ============================================================
// K3: EDT pass along D (windowed) for out+in fields + sdf*prob
// reduction. One block per (pair, h).
// ============================================================
__global__ void __launch_bounds__(512) k3_passD() {
    __shared__ float red[16];
    const int unit = blockIdx.x;
    const int p = unit >> 6;
    const int h = unit & 63;
    const int tid = threadIdx.x;
    const int w = tid & 63;
    const int c = (tid >> 6) * 8;

    const __half* baseO = g_F2h + (size_t)(2 * p) * SVOL + (size_t)h * 64 + w;
    const __half* baseI = baseO + SVOL;

    float ao[8], ai[8];
    dt8<4096>(baseO, c, ao);
    dt8<4096>(baseI, c, ai);

    const __half* pp = g_probh + (size_t)p * SVOL + (size_t)c * 4096 + (size_t)h * 64 + w;
    float local = 0.f;
#pragma unroll
    for (int t = 0; t < 8; t++) {
        const float sdf = sqrt_ap(ao[t]) - sqrt_ap(ai[t]);
        const float pr = __half2float(pp[(size_t)t * 4096]);
        local = fmaf(sdf, pr, local);
    }

#pragma unroll
    for (int o = 16; o > 0; o >>= 1) local += __shfl_down_sync(0xFFFFFFFFu, local, o);
    if ((tid & 31) == 0) red[tid >> 5] = local;
    __syncthreads();
    if (tid == 0) {
        float sum = 0.f;
#pragma unroll
        for (int k = 0; k < 16; k++) sum += red[k];
        atomicAdd(&g_bsum[p], sum);
    }
}

// ============================================================
// K4: assemble scalar loss
// ============================================================
__global__ void k4_final(float* out) {
    if (threadIdx.x == 0) {
        float dice = 0.f;
        for (int bc = 0; bc < 16; bc++) {
            const float TP = g_TP[bc], PS = g_PS[bc], CNT = g_CNT[bc];
            const float FP = PS - TP;
            const float FN = CNT - TP;
            dice += (TP + SMOOTHV) / (TP + 0.3f * FP + 0.7f * FN + SMOOTHV);
        }
        const float l_dice = 1.0f - dice / 16.0f;
        const float l_main = g_focal / (float)NTOT;

        float bacc = 0.f;
        for (int p = 0; p < NPAIR; p++) {
            const int b = p / 3, c = p % 3 + 1;
            const float cnt = g_CNT[b * 4 + c];
            if (cnt > 0.f) {
                float contrib;
                if (cnt >= (float)SVOL)
                    contrib = -g_PS[b * 4 + c] / (float)SVOL;   // sdf == -1 everywhere
                else
                    contrib = g_bsum[p] / (float)SVOL;
                bacc += contrib;
            }
        }
        const float l_bound = bacc / (12.0f + 1e-8f);
        out[0] = l_dice + l_main + 0.01f * l_bound;
    }
}

extern "C" void kernel_launch(void* const* d_in, const int* in_sizes, int n_in,
                              void* d_out, int out_size) {
    const float* preds = (const float*)d_in[0];
    const int*   tgt   = (const int*)d_in[1];
    (void)in_sizes; (void)n_in; (void)out_size;

    k0_init<<<1, 256>>>(tgt);
    k1_main<<<NTOT / 256, 256>>>(preds, tgt);
    k2_passH<<<NVOL * 64, 512>>>();
    k3_passD<<<NPAIR * 64, 512>>>();
    k4_final<<<1, 32>>>((float*)d_out);
}

// round 7
// speedup vs baseline: 2.3497x; 1.0475x over previous
#include <cuda_runtime.h>
#include <cuda_fp16.h>
#include <cstdint>

#define DIMS 64
#define SVOL (64*64*64)
#define NBATCH 4
#define NCLASS 4
#define NPAIR 12
#define NVOL 24
#define NTOT (NBATCH*SVOL)
#define SMOOTHV 1e-5f

__device__ __half g_Fh [(size_t)NVOL * SVOL];    // pass-1 line distances (fp16, exact ints)
__device__ __half g_F2h[(size_t)NVOL * SVOL];    // pass-2 2D distances (fp16)
__device__ __half g_probh[(size_t)NPAIR * SVOL]; // probs classes 1..3 (fp16)
__device__ float g_TP[16];
__device__ float g_PS[16];
__device__ float g_CNT[16];
__device__ float g_focal;
__device__ float g_bsum[NPAIR];
__device__ int   g_flag64;

__device__ __forceinline__ float sqrt_ap(float x) {
    float y; asm("sqrt.approx.f32 %0, %1;" : "=f"(y) : "f"(x)); return y;
}

// ============================================================
// K0: zero accumulators + int64-vs-int32 targets detection
// ============================================================
__global__ void k0_init(const int* __restrict__ tgt32) {
    int t = threadIdx.x;
    __shared__ int any;
    if (t == 0) any = 0;
    __syncthreads();
    int v = tgt32[2 * t + 1];
    if (v != 0) atomicOr(&any, 1);
    __syncthreads();
    if (t == 0) g_flag64 = (any == 0) ? 1 : 0;
    if (t < 16) { g_TP[t] = 0.f; g_PS[t] = 0.f; g_CNT[t] = 0.f; }
    if (t < NPAIR) g_bsum[t] = 0.f;
    if (t == 0) g_focal = 0.f;
}

// nearest set-bit distance within a 64-bit line mask
__device__ __forceinline__ float ndist(unsigned long long M, int i) {
    if (M == 0ULL) return __int_as_float(0x7f800000);   // +inf
    unsigned long long L = M << (63 - i);
    int dl = L ? __clzll((long long)L) : 9999;
    unsigned long long R = M >> i;
    int dr = R ? (__ffsll((long long)R) - 1) : 9999;
    return (float)min(dl, dr);
}

// ============================================================
// K1: softmax, focal, Tversky partials, prob store (fp16),
//     EDT pass-1 along W via ballot bitmasks -> fp16 distances
// ============================================================
__global__ void __launch_bounds__(256) k1_main(const float* __restrict__ preds,
                                               const int* __restrict__ tgt32) {
    const int tid = threadIdx.x;
    const int g = blockIdx.x * 256 + tid;
    const int b = g >> 18;
    const int s = g & (SVOL - 1);

    const int f64 = g_flag64;
    const int t = tgt32[f64 ? (g << 1) : g];

    const float x0 = preds[(size_t)(b * 4 + 0) * SVOL + s];
    const float x1 = preds[(size_t)(b * 4 + 1) * SVOL + s];
    const float x2 = preds[(size_t)(b * 4 + 2) * SVOL + s];
    const float x3 = preds[(size_t)(b * 4 + 3) * SVOL + s];

    const float m  = fmaxf(fmaxf(x0, x1), fmaxf(x2, x3));
    const float e0 = __expf(x0 - m), e1 = __expf(x1 - m);
    const float e2 = __expf(x2 - m), e3 = __expf(x3 - m);
    const float se = e0 + e1 + e2 + e3;
    const float inv = __fdividef(1.0f, se);
    const float p0 = e0 * inv, p1 = e1 * inv, p2 = e2 * inv, p3 = e3 * inv;

    const float xt = (t == 0) ? x0 : (t == 1) ? x1 : (t == 2) ? x2 : x3;
    const float ce = -(xt - m - __logf(se));
    const float pt = (t == 0) ? p0 : (t == 1) ? p1 : (t == 2) ? p2 : p3;
    const float om = 1.0f - pt;
    const float focal = om * om * ce;

    g_probh[(size_t)(b * 3 + 0) * SVOL + s] = __float2half(p1);
    g_probh[(size_t)(b * 3 + 1) * SVOL + s] = __float2half(p2);
    g_probh[(size_t)(b * 3 + 2) * SVOL + s] = __float2half(p3);

    // ---- EDT pass-1 along W via line bitmasks ----
    const unsigned full = 0xFFFFFFFFu;
    const unsigned bal1 = __ballot_sync(full, t == 1);
    const unsigned bal2 = __ballot_sync(full, t == 2);
    const unsigned bal3 = __ballot_sync(full, t == 3);
    __shared__ unsigned sb[3][8];
    const int wid = tid >> 5;
    if ((tid & 31) == 0) { sb[0][wid] = bal1; sb[1][wid] = bal2; sb[2][wid] = bal3; }
    __syncthreads();

    const int line = tid >> 6;
    const int i = tid & 63;
#pragma unroll
    for (int cm = 0; cm < 3; cm++) {
        unsigned long long M = (unsigned long long)sb[cm][line * 2] |
                               ((unsigned long long)sb[cm][line * 2 + 1] << 32);
        const int v = (b * 3 + cm) * 2;
        g_Fh[(size_t)v * SVOL + s]       = __float2half(ndist(M, i));
        g_Fh[(size_t)(v + 1) * SVOL + s] = __float2half(ndist(~M, i));
    }

    float vals[13];
    vals[0] = (t == 0) ? p0 : 0.f;
    vals[1] = (t == 1) ? p1 : 0.f;
    vals[2] = (t == 2) ? p2 : 0.f;
    vals[3] = (t == 3) ? p3 : 0.f;
    vals[4] = p0; vals[5] = p1; vals[6] = p2; vals[7] = p3;
    vals[8]  = (t == 0) ? 1.f : 0.f;
    vals[9]  = (t == 1) ? 1.f : 0.f;
    vals[10] = (t == 2) ? 1.f : 0.f;
    vals[11] = (t == 3) ? 1.f : 0.f;
    vals[12] = focal;

    __shared__ float red[13 * 8];
#pragma unroll
    for (int q = 0; q < 13; q++) {
        float v = vals[q];
#pragma unroll
        for (int o = 16; o > 0; o >>= 1) v += __shfl_down_sync(full, v, o);
        if ((tid & 31) == 0) red[q * 8 + wid] = v;
    }
    __syncthreads();
    if (tid < 13) {
        float sum = 0.f;
#pragma unroll
        for (int k = 0; k < 8; k++) sum += red[tid * 8 + k];
        if (tid < 4)       atomicAdd(&g_TP[b * 4 + tid], sum);
        else if (tid < 8)  atomicAdd(&g_PS[b * 4 + tid - 4], sum);
        else if (tid < 12) atomicAdd(&g_CNT[b * 4 + tid - 8], sum);
        else               atomicAdd(&g_focal, sum);
    }
}

// ============================================================
// Windowed exact 1D DT over 8 rows x 2 adjacent columns,
// packed half2 arithmetic. Window +-3; any skipped candidate
// has (i-j)^2 >= 16, so results <= 16 are provably exact
// (and exact in fp16: all candidates <= 2048 are exact ints).
// Outputs > 16 trigger an exact fp32 full 64-scan fallback.
// ============================================================
template<int HSTRIDE>   // element stride between rows, in halves (even)
__device__ __forceinline__ void dt8v(const __half* __restrict__ base, int c, float2 acc[8]) {
    const __half2* b2 = reinterpret_cast<const __half2*>(base);
    const int S2 = HSTRIDE / 2;
    const __half2 inf2 = __halves2half2(__ushort_as_half(0x7C00), __ushort_as_half(0x7C00));
    __half2 s[14];
#pragma unroll
    for (int mi = 0; mi < 14; mi++) {
        int j = c - 3 + mi;
        if (j >= 0 && j < 64) {
            __half2 v = b2[(size_t)j * S2];
            s[mi] = __hmul2(v, v);
        } else s[mi] = inf2;
    }
    const __half2 c1 = __float2half2_rn(1.f);
    const __half2 c4 = __float2half2_rn(4.f);
    const __half2 c9 = __float2half2_rn(9.f);
    __half2 a2[8];
#pragma unroll
    for (int t = 0; t < 8; t++) {
        __half2 a = s[t + 3];
        a = __hmin2(a, __hadd2(s[t + 2], c1)); a = __hmin2(a, __hadd2(s[t + 4], c1));
        a = __hmin2(a, __hadd2(s[t + 1], c4)); a = __hmin2(a, __hadd2(s[t + 5], c4));
        a = __hmin2(a, __hadd2(s[t + 0], c9)); a = __hmin2(a, __hadd2(s[t + 6], c9));
        a2[t] = a;
    }
    __half2 mx2 = a2[0];
#pragma unroll
    for (int t = 1; t < 8; t++) mx2 = __hmax2(mx2, a2[t]);
#pragma unroll
    for (int t = 0; t < 8; t++) acc[t] = __half22float2(a2[t]);
    const float fmx = fmaxf(__low2float(mx2), __high2float(mx2));
    if (__any_sync(0xFFFFFFFFu, fmx > 16.0f)) {
        // exact fp32 fallback: full scan (min is idempotent over window result)
        float jf = 0.f;
        for (int j = 0; j < 64; j++, jf += 1.0f) {
            const float f0 = __half2float(base[(size_t)j * HSTRIDE]);
            const float f1 = __half2float(base[(size_t)j * HSTRIDE + 1]);
            const float q0 = f0 * f0, q1 = f1 * f1;
#pragma unroll
            for (int t = 0; t < 8; t++) {
                const float dk = (float)(c + t) - jf;
                const float d2 = dk * dk;
                acc[t].x = fminf(acc[t].x, d2 + q0);
                acc[t].y = fminf(acc[t].y, d2 + q1);
            }
        }
    }
}

// ============================================================
// K2: EDT pass along H (g_Fh -> g_F2h), windowed half2.
// One block per (volume, d) slice; thread owns 8 rows x 2 cols.
// ============================================================
__global__ void __launch_bounds__(256) k2_passH() {
    const int unit = blockIdx.x;
    const int v = unit >> 6;
    const int d = unit & 63;
    const int tid = threadIdx.x;
    const int w2 = (tid & 31) * 2;
    const int c = (tid >> 5) * 8;

    const __half* base = g_Fh + (size_t)v * SVOL + (size_t)d * 4096 + w2;
    float2 acc[8];
    dt8v<64>(base, c, acc);

    __half* dst = g_F2h + (size_t)v * SVOL + (size_t)d * 4096 + (size_t)c * 64 + w2;
#pragma unroll
    for (int t = 0; t < 8; t++) {
        __half2 o = __halves2half2(__float2half(sqrt_ap(acc[t].x)),
                                   __float2half(sqrt_ap(acc[t].y)));
        *reinterpret_cast<__half2*>(dst + (size_t)t * 64) = o;
    }
}

// ============================================================
// K3: EDT pass along D (windowed half2) for out+in fields +
// sdf*prob reduction. One block per (pair, h).
// ============================================================
__global__ void __launch_bounds__(256) k3_passD() {
    __shared__ float red[8];
    const int unit = blockIdx.x;
    const int p = unit >> 6;
    const int h = unit & 63;
    const int tid = threadIdx.x;
    const int w2 = (tid & 31) * 2;
    const int c = (tid >> 5) * 8;

    const __half* baseO = g_F2h + (size_t)(2 * p) * SVOL + (size_t)h * 64 + w2;
    const __half* baseI = baseO + SVOL;

    float2 ao[8], ai[8];
    dt8v<4096>(baseO, c, ao);
    dt8v<4096>(baseI, c, ai);

    const __half* pp = g_probh + (size_t)p * SVOL + (size_t)c * 4096 + (size_t)h * 64 + w2;
    float local = 0.f;
#pragma unroll
    for (int t = 0; t < 8; t++) {
        const float2 pr = __half22float2(*reinterpret_cast<const __half2*>(pp + (size_t)t * 4096));
        const float s0 = sqrt_ap(ao[t].x) - sqrt_ap(ai[t].x);
        const float s1 = sqrt_ap(ao[t].y) - sqrt_ap(ai[t].y);
        local = fmaf(s0, pr.x, local);
        local = fmaf(s1, pr.y, local);
    }

#pragma unroll
    for (int o = 16; o > 0; o >>= 1) local += __shfl_down_sync(0xFFFFFFFFu, local, o);
    if ((tid & 31) == 0) red[tid >> 5] = local;
    __syncthreads();
    if (tid == 0) {
        float sum = 0.f;
#pragma unroll
        for (int k = 0; k < 8; k++) sum += red[k];
        atomicAdd(&g_bsum[p], sum);
    }
}

// ============================================================
// K4: assemble scalar loss
// ============================================================
__global__ void k4_final(float* out) {
    if (threadIdx.x == 0) {
        float dice = 0.f;
        for (int bc = 0; bc < 16; bc++) {
            const float TP = g_TP[bc], PS = g_PS[bc], CNT = g_CNT[bc];
            const float FP = PS - TP;
            const float FN = CNT - TP;
            dice += (TP + SMOOTHV) / (TP + 0.3f * FP + 0.7f * FN + SMOOTHV);
        }
        const float l_dice = 1.0f - dice / 16.0f;
        const float l_main = g_focal / (float)NTOT;

        float bacc = 0.f;
        for (int p = 0; p < NPAIR; p++) {
            const int b = p / 3, c = p % 3 + 1;
            const float cnt = g_CNT[b * 4 + c];
            if (cnt > 0.f) {
                float contrib;
                if (cnt >= (float)SVOL)
                    contrib = -g_PS[b * 4 + c] / (float)SVOL;   // sdf == -1 everywhere
                else
                    contrib = g_bsum[p] / (float)SVOL;
                bacc += contrib;
            }
        }
        const float l_bound = bacc / (12.0f + 1e-8f);
        out[0] = l_dice + l_main + 0.01f * l_bound;
    }
}

extern "C" void kernel_launch(void* const* d_in, const int* in_sizes, int n_in,
                              void* d_out, int out_size) {
    const float* preds = (const float*)d_in[0];
    const int*   tgt   = (const int*)d_in[1];
    (void)in_sizes; (void)n_in; (void)out_size;

    k0_init<<<1, 256>>>(tgt);
    k1_main<<<NTOT / 256, 256>>>(preds, tgt);
    k2_passH<<<NVOL * 64, 256>>>();
    k3_passD<<<NPAIR * 64, 256>>>();
    k4_final<<<1, 32>>>((float*)d_out);
}

// round 8
// speedup vs baseline: 2.5614x; 1.0901x over previous
#include <cuda_runtime.h>
#include <cuda_fp16.h>
#include <cstdint>

#define DIMS 64
#define SVOL (64*64*64)
#define NBATCH 4
#define NCLASS 4
#define NPAIR 12
#define NVOL 24
#define NTOT (NBATCH*SVOL)
#define SMOOTHV 1e-5f

__device__ __half g_F2h[(size_t)NVOL * SVOL];    // pass-2 2D distances (fp16)
__device__ __half g_probh[(size_t)NPAIR * SVOL]; // probs classes 1..3 (fp16)
__device__ float g_TP[16];
__device__ float g_PS[16];
__device__ float g_CNT[16];
__device__ float g_focal;
__device__ float g_bsum[NPAIR];
__device__ int   g_flag64;

__device__ __forceinline__ float sqrt_ap(float x) {
    float y; asm("sqrt.approx.f32 %0, %1;" : "=f"(y) : "f"(x)); return y;
}

// ============================================================
// K0: zero accumulators + int64-vs-int32 targets detection
// ============================================================
__global__ void k0_init(const int* __restrict__ tgt32) {
    int t = threadIdx.x;
    __shared__ int any;
    if (t == 0) any = 0;
    __syncthreads();
    int v = tgt32[2 * t + 1];
    if (v != 0) atomicOr(&any, 1);
    __syncthreads();
    if (t == 0) g_flag64 = (any == 0) ? 1 : 0;
    if (t < 16) { g_TP[t] = 0.f; g_PS[t] = 0.f; g_CNT[t] = 0.f; }
    if (t < NPAIR) g_bsum[t] = 0.f;
    if (t == 0) g_focal = 0.f;
}

// nearest set-bit distance within a 64-bit line mask
__device__ __forceinline__ float ndist(unsigned long long M, int i) {
    if (M == 0ULL) return __int_as_float(0x7f800000);   // +inf
    unsigned long long L = M << (63 - i);
    int dl = L ? __clzll((long long)L) : 9999;
    unsigned long long R = M >> i;
    int dr = R ? (__ffsll((long long)R) - 1) : 9999;
    return (float)min(dl, dr);
}

// ============================================================
// Windowed exact 1D DT over 8 rows x 2 adjacent columns,
// packed half2. Results <= 16 are provably exact; otherwise
// the warp takes an exact fp32 full 64-scan fallback.
// ============================================================
template<int HSTRIDE>
__device__ __forceinline__ void dt8v(const __half* __restrict__ base, int c, float2 acc[8]) {
    const __half2* b2 = reinterpret_cast<const __half2*>(base);
    const int S2 = HSTRIDE / 2;
    const __half2 inf2 = __halves2half2(__ushort_as_half(0x7C00), __ushort_as_half(0x7C00));
    __half2 s[14];
#pragma unroll
    for (int mi = 0; mi < 14; mi++) {
        int j = c - 3 + mi;
        if (j >= 0 && j < 64) {
            __half2 v = b2[(size_t)j * S2];
            s[mi] = __hmul2(v, v);
        } else s[mi] = inf2;
    }
    const __half2 c1 = __float2half2_rn(1.f);
    const __half2 c4 = __float2half2_rn(4.f);
    const __half2 c9 = __float2half2_rn(9.f);
    __half2 a2[8];
#pragma unroll
    for (int t = 0; t < 8; t++) {
        __half2 a = s[t + 3];
        a = __hmin2(a, __hadd2(s[t + 2], c1)); a = __hmin2(a, __hadd2(s[t + 4], c1));
        a = __hmin2(a, __hadd2(s[t + 1], c4)); a = __hmin2(a, __hadd2(s[t + 5], c4));
        a = __hmin2(a, __hadd2(s[t + 0], c9)); a = __hmin2(a, __hadd2(s[t + 6], c9));
        a2[t] = a;
    }
    __half2 mx2 = a2[0];
#pragma unroll
    for (int t = 1; t < 8; t++) mx2 = __hmax2(mx2, a2[t]);
#pragma unroll
    for (int t = 0; t < 8; t++) acc[t] = __half22float2(a2[t]);
    const float fmx = fmaxf(__low2float(mx2), __high2float(mx2));
    if (__any_sync(0xFFFFFFFFu, fmx > 16.0f)) {
        float jf = 0.f;
        for (int j = 0; j < 64; j++, jf += 1.0f) {
            const float f0 = __half2float(base[(size_t)j * HSTRIDE]);
            const float f1 = __half2float(base[(size_t)j * HSTRIDE + 1]);
            const float q0 = f0 * f0, q1 = f1 * f1;
#pragma unroll
            for (int t = 0; t < 8; t++) {
                const float dk = (float)(c + t) - jf;
                const float d2 = dk * dk;
                acc[t].x = fminf(acc[t].x, d2 + q0);
                acc[t].y = fminf(acc[t].y, d2 + q1);
            }
        }
    }
}

// ============================================================
// K12 fused: one block per (b, d) slice, 512 threads.
//  A: softmax/focal/Tversky partials + probh store + ballots
//  B: pass-1 line distances -> SMEM tiles (6 volumes, fp16)
//  C: pass-2 windowed DT along H from SMEM -> g_F2h
//  D: block reduction of the 13 scalars
// ============================================================
__global__ void __launch_bounds__(512) k12_fused(const float* __restrict__ preds,
                                                 const int* __restrict__ tgt32) {
    extern __shared__ __half T[];            // 6 * 4096 halves = 48 KB
    __shared__ unsigned sball[3][64][2];
    __shared__ float red[13 * 16];
    const int tid = threadIdx.x;
    const int b = blockIdx.x >> 6;
    const int d = blockIdx.x & 63;
    const int f64 = g_flag64;
    const unsigned full = 0xFFFFFFFFu;
    const int wid = tid >> 5;

    float a13[13];
#pragma unroll
    for (int q = 0; q < 13; q++) a13[q] = 0.f;

    // ---------- Phase A ----------
#pragma unroll
    for (int r = 0; r < 8; r++) {
        const int sl = tid + r * 512;
        const int s = d * 4096 + sl;
        const int gidx = b * SVOL + s;
        const int t = tgt32[f64 ? (gidx << 1) : gidx];

        const float x0 = preds[(size_t)(b * 4 + 0) * SVOL + s];
        const float x1 = preds[(size_t)(b * 4 + 1) * SVOL + s];
        const float x2 = preds[(size_t)(b * 4 + 2) * SVOL + s];
        const float x3 = preds[(size_t)(b * 4 + 3) * SVOL + s];

        const float m  = fmaxf(fmaxf(x0, x1), fmaxf(x2, x3));
        const float e0 = __expf(x0 - m), e1 = __expf(x1 - m);
        const float e2 = __expf(x2 - m), e3 = __expf(x3 - m);
        const float se = e0 + e1 + e2 + e3;
        const float inv = __fdividef(1.0f, se);
        const float p0 = e0 * inv, p1 = e1 * inv, p2 = e2 * inv, p3 = e3 * inv;

        const float xt = (t == 0) ? x0 : (t == 1) ? x1 : (t == 2) ? x2 : x3;
        const float ce = -(xt - m - __logf(se));
        const float pt = (t == 0) ? p0 : (t == 1) ? p1 : (t == 2) ? p2 : p3;
        const float om = 1.0f - pt;

        g_probh[(size_t)(b * 3 + 0) * SVOL + s] = __float2half(p1);
        g_probh[(size_t)(b * 3 + 1) * SVOL + s] = __float2half(p2);
        g_probh[(size_t)(b * 3 + 2) * SVOL + s] = __float2half(p3);

        a13[0] += (t == 0) ? p0 : 0.f;
        a13[1] += (t == 1) ? p1 : 0.f;
        a13[2] += (t == 2) ? p2 : 0.f;
        a13[3] += (t == 3) ? p3 : 0.f;
        a13[4] += p0; a13[5] += p1; a13[6] += p2; a13[7] += p3;
        a13[8]  += (t == 0) ? 1.f : 0.f;
        a13[9]  += (t == 1) ? 1.f : 0.f;
        a13[10] += (t == 2) ? 1.f : 0.f;
        a13[11] += (t == 3) ? 1.f : 0.f;
        a13[12] += om * om * ce;

        const unsigned bal1 = __ballot_sync(full, t == 1);
        const unsigned bal2 = __ballot_sync(full, t == 2);
        const unsigned bal3 = __ballot_sync(full, t == 3);
        if ((tid & 31) == 0) {
            const int h = r * 8 + (wid >> 1);
            const int hf = wid & 1;
            sball[0][h][hf] = bal1;
            sball[1][h][hf] = bal2;
            sball[2][h][hf] = bal3;
        }
    }
    __syncthreads();

    // ---------- Phase B: pass-1 line distances into SMEM ----------
    {
        const int h = tid >> 3;
        const int w0 = (tid & 7) * 8;
#pragma unroll
        for (int cm = 0; cm < 3; cm++) {
            const unsigned long long M = (unsigned long long)sball[cm][h][0] |
                                         ((unsigned long long)sball[cm][h][1] << 32);
            const unsigned long long Mn = ~M;
            __half* t0 = T + (cm * 2 + 0) * 4096 + h * 64;
            __half* t1 = T + (cm * 2 + 1) * 4096 + h * 64;
#pragma unroll
            for (int q = 0; q < 8; q++) {
                const int w = w0 + q;
                t0[w] = __float2half(ndist(M, w));
                t1[w] = __float2half(ndist(Mn, w));
            }
        }
    }
    __syncthreads();

    // ---------- Phase C: windowed DT along H, SMEM -> g_F2h ----------
    {
        const int w2 = (tid & 31) * 2;
        const int c = ((tid >> 5) & 7) * 8;
        const int vh = tid >> 8;             // 0..1
#pragma unroll
        for (int vi = 0; vi < 3; vi++) {
            const int vol = vh * 3 + vi;
            const __half* base = T + vol * 4096 + w2;
            float2 acc[8];
            dt8v<64>(base, c, acc);
            __half* dst = g_F2h + (size_t)(b * 6 + vol) * SVOL + (size_t)d * 4096 +
                          (size_t)c * 64 + w2;
#pragma unroll
            for (int t = 0; t < 8; t++) {
                __half2 o = __halves2half2(__float2half(sqrt_ap(acc[t].x)),
                                           __float2half(sqrt_ap(acc[t].y)));
                *reinterpret_cast<__half2*>(dst + (size_t)t * 64) = o;
            }
        }
    }

    // ---------- Phase D: block reduction ----------
#pragma unroll
    for (int q = 0; q < 13; q++) {
        float v = a13[q];
#pragma unroll
        for (int o = 16; o > 0; o >>= 1) v += __shfl_down_sync(full, v, o);
        if ((tid & 31) == 0) red[q * 16 + wid] = v;
    }
    __syncthreads();
    if (tid < 13) {
        float sum = 0.f;
#pragma unroll
        for (int k = 0; k < 16; k++) sum += red[tid * 16 + k];
        if (tid < 4)       atomicAdd(&g_TP[b * 4 + tid], sum);
        else if (tid < 8)  atomicAdd(&g_PS[b * 4 + tid - 4], sum);
        else if (tid < 12) atomicAdd(&g_CNT[b * 4 + tid - 8], sum);
        else               atomicAdd(&g_focal, sum);
    }
}

// ============================================================
// K3: EDT pass along D (windowed half2) + sdf*prob reduction
// ============================================================
__global__ void __launch_bounds__(256) k3_passD() {
    __shared__ float red[8];
    const int unit = blockIdx.x;
    const int p = unit >> 6;
    const int h = unit & 63;
    const int tid = threadIdx.x;
    const int w2 = (tid & 31) * 2;
    const int c = (tid >> 5) * 8;

    const __half* baseO = g_F2h + (size_t)(2 * p) * SVOL + (size_t)h * 64 + w2;
    const __half* baseI = baseO + SVOL;

    float2 ao[8], ai[8];
    dt8v<4096>(baseO, c, ao);
    dt8v<4096>(baseI, c, ai);

    const __half* pp = g_probh + (size_t)p * SVOL + (size_t)c * 4096 + (size_t)h * 64 + w2;
    float local = 0.f;
#pragma unroll
    for (int t = 0; t < 8; t++) {
        const float2 pr = __half22float2(*reinterpret_cast<const __half2*>(pp + (size_t)t * 4096));
        const float s0 = sqrt_ap(ao[t].x) - sqrt_ap(ai[t].x);
        const float s1 = sqrt_ap(ao[t].y) - sqrt_ap(ai[t].y);
        local = fmaf(s0, pr.x, local);
        local = fmaf(s1, pr.y, local);
    }

#pragma unroll
    for (int o = 16; o > 0; o >>= 1) local += __shfl_down_sync(0xFFFFFFFFu, local, o);
    if ((tid & 31) == 0) red[tid >> 5] = local;
    __syncthreads();
    if (tid == 0) {
        float sum = 0.f;
#pragma unroll
        for (int k = 0; k < 8; k++) sum += red[k];
        atomicAdd(&g_bsum[p], sum);
    }
}

// ============================================================
// K4: assemble scalar loss
// ============================================================
__global__ void k4_final(float* out) {
    if (threadIdx.x == 0) {
        float dice = 0.f;
        for (int bc = 0; bc < 16; bc++) {
            const float TP = g_TP[bc], PS = g_PS[bc], CNT = g_CNT[bc];
            const float FP = PS - TP;
            const float FN = CNT - TP;
            dice += (TP + SMOOTHV) / (TP + 0.3f * FP + 0.7f * FN + SMOOTHV);
        }
        const float l_dice = 1.0f - dice / 16.0f;
        const float l_main = g_focal / (float)NTOT;

        float bacc = 0.f;
        for (int p = 0; p < NPAIR; p++) {
            const int b = p / 3, c = p % 3 + 1;
            const float cnt = g_CNT[b * 4 + c];
            if (cnt > 0.f) {
                float contrib;
                if (cnt >= (float)SVOL)
                    contrib = -g_PS[b * 4 + c] / (float)SVOL;
                else
                    contrib = g_bsum[p] / (float)SVOL;
                bacc += contrib;
            }
        }
        const float l_bound = bacc / (12.0f + 1e-8f);
        out[0] = l_dice + l_main + 0.01f * l_bound;
    }
}

extern "C" void kernel_launch(void* const* d_in, const int* in_sizes, int n_in,
                              void* d_out, int out_size) {
    const float* preds = (const float*)d_in[0];
    const int*   tgt   = (const int*)d_in[1];
    (void)in_sizes; (void)n_in; (void)out_size;

    const int smem = 6 * 4096 * (int)sizeof(__half);   // 48 KB dynamic
    cudaFuncSetAttribute(k12_fused, cudaFuncAttributeMaxDynamicSharedMemorySize, smem);

    k0_init<<<1, 256>>>(tgt);
    k12_fused<<<NBATCH * 64, 512, smem>>>(preds, tgt);
    k3_passD<<<NPAIR * 64, 256>>>();
    k4_final<<<1, 32>>>((float*)d_out);
}

// round 9
// speedup vs baseline: 2.6093x; 1.0187x over previous
#include <cuda_runtime.h>
#include <cuda_fp16.h>
#include <cstdint>

#define DIMS 64
#define SVOL (64*64*64)
#define NBATCH 4
#define NCLASS 4
#define NPAIR 12
#define NVOL 24
#define NTOT (NBATCH*SVOL)
#define SMOOTHV 1e-5f
#define K3_GRID (NPAIR * 64)

__device__ __half g_F2h[(size_t)NVOL * SVOL];    // pass-2 2D distances (fp16)
__device__ __half g_probh[(size_t)NPAIR * SVOL]; // probs classes 1..3 (fp16)
__device__ float g_TP[16];
__device__ float g_PS[16];
__device__ float g_CNT[16];
__device__ float g_focal;
__device__ float g_bsum[NPAIR];
__device__ int   g_flag64;
__device__ unsigned g_done;

__device__ __forceinline__ float sqrt_ap(float x) {
    float y; asm("sqrt.approx.f32 %0, %1;" : "=f"(y) : "f"(x)); return y;
}

// ============================================================
// K0: zero accumulators + int64-vs-int32 targets detection
// ============================================================
__global__ void k0_init(const int* __restrict__ tgt32) {
    int t = threadIdx.x;
    __shared__ int any;
    if (t == 0) any = 0;
    __syncthreads();
    int v = tgt32[2 * t + 1];
    if (v != 0) atomicOr(&any, 1);
    __syncthreads();
    if (t == 0) g_flag64 = (any == 0) ? 1 : 0;
    if (t < 16) { g_TP[t] = 0.f; g_PS[t] = 0.f; g_CNT[t] = 0.f; }
    if (t < NPAIR) g_bsum[t] = 0.f;
    if (t == 0) { g_focal = 0.f; g_done = 0u; }
}

// nearest set-bit distance within a 64-bit line mask
__device__ __forceinline__ float ndist(unsigned long long M, int i) {
    if (M == 0ULL) return __int_as_float(0x7f800000);   // +inf
    unsigned long long L = M << (63 - i);
    int dl = L ? __clzll((long long)L) : 9999;
    unsigned long long R = M >> i;
    int dr = R ? (__ffsll((long long)R) - 1) : 9999;
    return (float)min(dl, dr);
}

// ============================================================
// Windowed exact 1D DT over 8 rows x 2 adjacent columns,
// packed half2. Results <= 16 are provably exact; otherwise
// the warp takes an exact fp32 full 64-scan fallback.
// ============================================================
template<int HSTRIDE>
__device__ __forceinline__ void dt8v(const __half* __restrict__ base, int c, float2 acc[8]) {
    const __half2* b2 = reinterpret_cast<const __half2*>(base);
    const int S2 = HSTRIDE / 2;
    const __half2 inf2 = __halves2half2(__ushort_as_half(0x7C00), __ushort_as_half(0x7C00));
    __half2 s[14];
#pragma unroll
    for (int mi = 0; mi < 14; mi++) {
        int j = c - 3 + mi;
        if (j >= 0 && j < 64) {
            __half2 v = b2[(size_t)j * S2];
            s[mi] = __hmul2(v, v);
        } else s[mi] = inf2;
    }
    const __half2 c1 = __float2half2_rn(1.f);
    const __half2 c4 = __float2half2_rn(4.f);
    const __half2 c9 = __float2half2_rn(9.f);
    __half2 a2[8];
#pragma unroll
    for (int t = 0; t < 8; t++) {
        __half2 a = s[t + 3];
        a = __hmin2(a, __hadd2(s[t + 2], c1)); a = __hmin2(a, __hadd2(s[t + 4], c1));
        a = __hmin2(a, __hadd2(s[t + 1], c4)); a = __hmin2(a, __hadd2(s[t + 5], c4));
        a = __hmin2(a, __hadd2(s[t + 0], c9)); a = __hmin2(a, __hadd2(s[t + 6], c9));
        a2[t] = a;
    }
    __half2 mx2 = a2[0];
#pragma unroll
    for (int t = 1; t < 8; t++) mx2 = __hmax2(mx2, a2[t]);
#pragma unroll
    for (int t = 0; t < 8; t++) acc[t] = __half22float2(a2[t]);
    const float fmx = fmaxf(__low2float(mx2), __high2float(mx2));
    if (__any_sync(0xFFFFFFFFu, fmx > 16.0f)) {
        float jf = 0.f;
        for (int j = 0; j < 64; j++, jf += 1.0f) {
            const float f0 = __half2float(base[(size_t)j * HSTRIDE]);
            const float f1 = __half2float(base[(size_t)j * HSTRIDE + 1]);
            const float q0 = f0 * f0, q1 = f1 * f1;
#pragma unroll
            for (int t = 0; t < 8; t++) {
                const float dk = (float)(c + t) - jf;
                const float d2 = dk * dk;
                acc[t].x = fminf(acc[t].x, d2 + q0);
                acc[t].y = fminf(acc[t].y, d2 + q1);
            }
        }
    }
}

// ============================================================
// K12 fused: one block per (b, d) slice, 512 threads.
//  A: softmax/focal/Tversky partials + probh store + ballots
//  B: pass-1 line distances -> SMEM tiles (6 volumes, fp16)
//  C: pass-2 windowed DT along H from SMEM -> g_F2h
//  D: block reduction of the 13 scalars
// ============================================================
__global__ void __launch_bounds__(512) k12_fused(const float* __restrict__ preds,
                                                 const int* __restrict__ tgt32) {
    extern __shared__ __half T[];            // 6 * 4096 halves = 48 KB
    __shared__ unsigned sball[3][64][2];
    __shared__ float red[13 * 16];
    const int tid = threadIdx.x;
    const int b = blockIdx.x >> 6;
    const int d = blockIdx.x & 63;
    const int f64 = g_flag64;
    const unsigned full = 0xFFFFFFFFu;
    const int wid = tid >> 5;

    float a13[13];
#pragma unroll
    for (int q = 0; q < 13; q++) a13[q] = 0.f;

    // ---------- Phase A ----------
#pragma unroll
    for (int r = 0; r < 8; r++) {
        const int sl = tid + r * 512;
        const int s = d * 4096 + sl;
        const int gidx = b * SVOL + s;
        const int t = tgt32[f64 ? (gidx << 1) : gidx];

        const float x0 = preds[(size_t)(b * 4 + 0) * SVOL + s];
        const float x1 = preds[(size_t)(b * 4 + 1) * SVOL + s];
        const float x2 = preds[(size_t)(b * 4 + 2) * SVOL + s];
        const float x3 = preds[(size_t)(b * 4 + 3) * SVOL + s];

        const float m  = fmaxf(fmaxf(x0, x1), fmaxf(x2, x3));
        const float e0 = __expf(x0 - m), e1 = __expf(x1 - m);
        const float e2 = __expf(x2 - m), e3 = __expf(x3 - m);
        const float se = e0 + e1 + e2 + e3;
        const float inv = __fdividef(1.0f, se);
        const float p0 = e0 * inv, p1 = e1 * inv, p2 = e2 * inv, p3 = e3 * inv;

        const float xt = (t == 0) ? x0 : (t == 1) ? x1 : (t == 2) ? x2 : x3;
        const float ce = -(xt - m - __logf(se));
        const float pt = (t == 0) ? p0 : (t == 1) ? p1 : (t == 2) ? p2 : p3;
        const float om = 1.0f - pt;

        g_probh[(size_t)(b * 3 + 0) * SVOL + s] = __float2half(p1);
        g_probh[(size_t)(b * 3 + 1) * SVOL + s] = __float2half(p2);
        g_probh[(size_t)(b * 3 + 2) * SVOL + s] = __float2half(p3);

        a13[0] += (t == 0) ? p0 : 0.f;
        a13[1] += (t == 1) ? p1 : 0.f;
        a13[2] += (t == 2) ? p2 : 0.f;
        a13[3] += (t == 3) ? p3 : 0.f;
        a13[4] += p0; a13[5] += p1; a13[6] += p2; a13[7] += p3;
        a13[8]  += (t == 0) ? 1.f : 0.f;
        a13[9]  += (t == 1) ? 1.f : 0.f;
        a13[10] += (t == 2) ? 1.f : 0.f;
        a13[11] += (t == 3) ? 1.f : 0.f;
        a13[12] += om * om * ce;

        const unsigned bal1 = __ballot_sync(full, t == 1);
        const unsigned bal2 = __ballot_sync(full, t == 2);
        const unsigned bal3 = __ballot_sync(full, t == 3);
        if ((tid & 31) == 0) {
            const int h = r * 8 + (wid >> 1);
            const int hf = wid & 1;
            sball[0][h][hf] = bal1;
            sball[1][h][hf] = bal2;
            sball[2][h][hf] = bal3;
        }
    }
    __syncthreads();

    // ---------- Phase B: pass-1 line distances into SMEM ----------
    {
        const int h = tid >> 3;
        const int w0 = (tid & 7) * 8;
#pragma unroll
        for (int cm = 0; cm < 3; cm++) {
            const unsigned long long M = (unsigned long long)sball[cm][h][0] |
                                         ((unsigned long long)sball[cm][h][1] << 32);
            const unsigned long long Mn = ~M;
            __half* t0 = T + (cm * 2 + 0) * 4096 + h * 64;
            __half* t1 = T + (cm * 2 + 1) * 4096 + h * 64;
#pragma unroll
            for (int q = 0; q < 8; q++) {
                const int w = w0 + q;
                t0[w] = __float2half(ndist(M, w));
                t1[w] = __float2half(ndist(Mn, w));
            }
        }
    }
    __syncthreads();

    // ---------- Phase C: windowed DT along H, SMEM -> g_F2h ----------
    {
        const int w2 = (tid & 31) * 2;
        const int c = ((tid >> 5) & 7) * 8;
        const int vh = tid >> 8;             // 0..1
#pragma unroll
        for (int vi = 0; vi < 3; vi++) {
            const int vol = vh * 3 + vi;
            const __half* base = T + vol * 4096 + w2;
            float2 acc[8];
            dt8v<64>(base, c, acc);
            __half* dst = g_F2h + (size_t)(b * 6 + vol) * SVOL + (size_t)d * 4096 +
                          (size_t)c * 64 + w2;
#pragma unroll
            for (int t = 0; t < 8; t++) {
                __half2 o = __halves2half2(__float2half(sqrt_ap(acc[t].x)),
                                           __float2half(sqrt_ap(acc[t].y)));
                *reinterpret_cast<__half2*>(dst + (size_t)t * 64) = o;
            }
        }
    }

    // ---------- Phase D: block reduction ----------
#pragma unroll
    for (int q = 0; q < 13; q++) {
        float v = a13[q];
#pragma unroll
        for (int o = 16; o > 0; o >>= 1) v += __shfl_down_sync(full, v, o);
        if ((tid & 31) == 0) red[q * 16 + wid] = v;
    }
    __syncthreads();
    if (tid < 13) {
        float sum = 0.f;
#pragma unroll
        for (int k = 0; k < 16; k++) sum += red[tid * 16 + k];
        if (tid < 4)       atomicAdd(&g_TP[b * 4 + tid], sum);
        else if (tid < 8)  atomicAdd(&g_PS[b * 4 + tid - 4], sum);
        else if (tid < 12) atomicAdd(&g_CNT[b * 4 + tid - 8], sum);
        else               atomicAdd(&g_focal, sum);
    }
}

// ============================================================
// K3: EDT pass along D (windowed half2) + sdf*prob reduction,
// with last-block final loss assembly (no separate K4 kernel).
// ============================================================
__global__ void __launch_bounds__(256) k3_passD(float* __restrict__ out) {
    __shared__ float red[8];
    __shared__ unsigned slast;
    const int unit = blockIdx.x;
    const int p = unit >> 6;
    const int h = unit & 63;
    const int tid = threadIdx.x;
    const int w2 = (tid & 31) * 2;
    const int c = (tid >> 5) * 8;

    const __half* baseO = g_F2h + (size_t)(2 * p) * SVOL + (size_t)h * 64 + w2;
    const __half* baseI = baseO + SVOL;

    float2 ao[8], ai[8];
    dt8v<4096>(baseO, c, ao);
    dt8v<4096>(baseI, c, ai);

    const __half* pp = g_probh + (size_t)p * SVOL + (size_t)c * 4096 + (size_t)h * 64 + w2;
    float local = 0.f;
#pragma unroll
    for (int t = 0; t < 8; t++) {
        const float2 pr = __half22float2(*reinterpret_cast<const __half2*>(pp + (size_t)t * 4096));
        const float s0 = sqrt_ap(ao[t].x) - sqrt_ap(ai[t].x);
        const float s1 = sqrt_ap(ao[t].y) - sqrt_ap(ai[t].y);
        local = fmaf(s0, pr.x, local);
        local = fmaf(s1, pr.y, local);
    }

#pragma unroll
    for (int o = 16; o > 0; o >>= 1) local += __shfl_down_sync(0xFFFFFFFFu, local, o);
    if ((tid & 31) == 0) red[tid >> 5] = local;
    __syncthreads();
    if (tid == 0) {
        float sum = 0.f;
#pragma unroll
        for (int k = 0; k < 8; k++) sum += red[k];
        atomicAdd(&g_bsum[p], sum);
        __threadfence();
        slast = atomicAdd(&g_done, 1u);
    }
    __syncthreads();

    // ---- last block assembles the scalar loss (first warp) ----
    if (slast == K3_GRID - 1 && tid < 32) {
        // parallel loads: lane bc < 16 handles one (b, class)
        float dterm = 0.f;
        if (tid < 16) {
            const float TP = g_TP[tid], PS = g_PS[tid], CNT = g_CNT[tid];
            const float FP = PS - TP;
            const float FN = CNT - TP;
            dterm = (TP + SMOOTHV) / (TP + 0.3f * FP + 0.7f * FN + SMOOTHV);
        }
        float bterm = 0.f;
        if (tid < NPAIR) {
            const int b = tid / 3, cc = tid % 3 + 1;
            const float cnt = g_CNT[b * 4 + cc];
            if (cnt > 0.f) {
                if (cnt >= (float)SVOL)
                    bterm = -g_PS[b * 4 + cc] / (float)SVOL;   // sdf == -1 everywhere
                else
                    bterm = g_bsum[tid] / (float)SVOL;
            }
        }
#pragma unroll
        for (int o = 16; o > 0; o >>= 1) {
            dterm += __shfl_down_sync(0xFFFFFFFFu, dterm, o);
            bterm += __shfl_down_sync(0xFFFFFFFFu, bterm, o);
        }
        if (tid == 0) {
            const float l_dice = 1.0f - dterm / 16.0f;
            const float l_main = g_focal / (float)NTOT;
            const float l_bound = bterm / (12.0f + 1e-8f);
            out[0] = l_dice + l_main + 0.01f * l_bound;
        }
    }
}

extern "C" void kernel_launch(void* const* d_in, const int* in_sizes, int n_in,
                              void* d_out, int out_size) {
    const float* preds = (const float*)d_in[0];
    const int*   tgt   = (const int*)d_in[1];
    (void)in_sizes; (void)n_in; (void)out_size;

    const int smem = 6 * 4096 * (int)sizeof(__half);   // 48 KB dynamic
    cudaFuncSetAttribute(k12_fused, cudaFuncAttributeMaxDynamicSharedMemorySize, smem);

    k0_init<<<1, 256>>>(tgt);
    k12_fused<<<NBATCH * 64, 512, smem>>>(preds, tgt);
    k3_passD<<<K3_GRID, 256>>>((float*)d_out);
}